// round 1
// baseline (speedup 1.0000x reference)
#include <cuda_runtime.h>

// Correlation (FlowNet): out[b, dy*21+dx, y, x] =
//   (1/256) * sum_c in1[b,c,y,x] * in2[b,c,y+dyo,x+dxo],  dyo,dxo in {-20,-18,...,20}
// B=8, C=256, H=96, W=128, zero padding outside the image.

#define B_SZ 8
#define C_SZ 256
#define H_SZ 96
#define W_SZ 128
#define G_SZ 21
#define CHUNK 8      // channels per smem stage
#define NWARP 7      // warps per block; each warp owns one dy
#define NTHREADS 224

// Shared memory layout (floats).
// A (in1 row), per channel: even x at [0,64), odd x at [80,144); stride 160.
//   (odd base offset 80 ==> +16 floats mod 32 vs even base -> conflict-free LDS.128)
#define A_CH_STRIDE 160
#define A_FLOATS (CHUNK * A_CH_STRIDE)          // 1280
// B (in2 rows), per (warp,channel) slot: positions p in [-20,147] split by parity:
//   even p at [0,84) via idx (p+20)/2 ; odd p at [112,196) via 112+(p+19)/2 ; stride 224.
#define B_SLOT 224
#define B_FLOATS (NWARP * CHUNK * B_SLOT)       // 12544
#define SMEM_FLOATS (A_FLOATS + B_FLOATS)       // 13824
#define SMEM_BYTES (SMEM_FLOATS * 4)            // 55296

__global__ __launch_bounds__(NTHREADS, 2)
void corr_kernel(const float* __restrict__ in1,
                 const float* __restrict__ in2,
                 float* __restrict__ out)
{
    extern __shared__ float smem[];
    float* As = smem;
    float* Bs = smem + A_FLOATS;

    const int dyt = blockIdx.x;   // 0..2  (dy triple)
    const int y   = blockIdx.y;   // 0..95
    const int b   = blockIdx.z;   // 0..7

    const int tid  = threadIdx.x;
    const int wid  = tid >> 5;    // 0..6  -> dy within triple
    const int lane = tid & 31;
    const int pi   = lane & 1;    // x parity
    const int g    = lane >> 1;   // x group: xb = 8*g + pi, thread covers xb+{0,2,4,6}

    const int dy_idx = dyt * NWARP + wid;   // 0..20
    // dyo = 2*dy_idx - 20 (applied in the B load via yy)

    float acc[4][21];
#pragma unroll
    for (int r = 0; r < 4; ++r)
#pragma unroll
        for (int d = 0; d < 21; ++d) acc[r][d] = 0.0f;

    // Zero the B buffer once: x halos and out-of-range dy rows stay zero forever.
    {
        float4 z = make_float4(0.f, 0.f, 0.f, 0.f);
        float4* b4 = (float4*)Bs;
#pragma unroll 1
        for (int i = tid; i < B_FLOATS / 4; i += NTHREADS) b4[i] = z;
    }
    __syncthreads();

    const float4* in1f4 = (const float4*)in1;
    const float4* in2f4 = (const float4*)in2;
    const int chan_f4 = (H_SZ * W_SZ) / 4;  // 3072 float4 per channel

#pragma unroll 1
    for (int c0 = 0; c0 < C_SZ; c0 += CHUNK) {
        // ---- stage A: in1[b, c0..c0+7, y, 0..127], parity-split ----
#pragma unroll 1
        for (int i = tid; i < CHUNK * 32; i += NTHREADS) {
            int cc = i >> 5, x4 = i & 31;
            float4 v = in1f4[((b * C_SZ + c0 + cc) * H_SZ + y) * (W_SZ / 4) + x4];
            float* ab = As + cc * A_CH_STRIDE;
            ((float2*)ab)[x4]        = make_float2(v.x, v.z);   // even x: 2*x4, 2*x4+1
            ((float2*)(ab + 80))[x4] = make_float2(v.y, v.w);   // odd  x
        }
        // ---- stage B: in2[b, c0..c0+7, y+dyo(w), 0..127] for 7 dy rows ----
#pragma unroll 1
        for (int i = tid; i < NWARP * CHUNK * 32; i += NTHREADS) {
            int w  = i >> 8;              // dy slot 0..6
            int rr = i & 255;
            int cc = rr >> 5, x4 = rr & 31;
            int yy = y + 2 * (dyt * NWARP + w) - 20;
            if ((unsigned)yy < (unsigned)H_SZ) {
                float4 v = in2f4[((b * C_SZ + c0 + cc) * H_SZ + yy) * (W_SZ / 4) + x4];
                float* bb = Bs + (w * CHUNK + cc) * B_SLOT;
                // valid positions p = 4*x4 + {0..3}: even idx = (p+20)/2 = 2*x4+10
                ((float2*)(bb + 10))[x4]  = make_float2(v.x, v.z);
                ((float2*)(bb + 122))[x4] = make_float2(v.y, v.w);
            }
        }
        __syncthreads();

        // ---- compute: 84 FMAs per thread per channel, 28 smem floats loaded ----
#pragma unroll 1
        for (int cc = 0; cc < CHUNK; ++cc) {
            float4 av = *(const float4*)(As + cc * A_CH_STRIDE + pi * 80 + 4 * g);
            float a0 = av.x, a1 = av.y, a2 = av.z, a3 = av.w;  // in1 at x = xb+0,2,4,6
            float wv[24];  // in2 positions xb-20 + 2k, k=0..23
            const float4* wp =
                (const float4*)(Bs + (wid * CHUNK + cc) * B_SLOT + pi * 112 + 4 * g);
#pragma unroll
            for (int j = 0; j < 6; ++j) {
                float4 t = wp[j];
                wv[4*j+0] = t.x; wv[4*j+1] = t.y; wv[4*j+2] = t.z; wv[4*j+3] = t.w;
            }
#pragma unroll
            for (int d = 0; d < 21; ++d) {
                acc[0][d] = fmaf(a0, wv[d + 0], acc[0][d]);
                acc[1][d] = fmaf(a1, wv[d + 1], acc[1][d]);
                acc[2][d] = fmaf(a2, wv[d + 2], acc[2][d]);
                acc[3][d] = fmaf(a3, wv[d + 3], acc[3][d]);
            }
        }
        __syncthreads();
    }

    // ---- epilogue: per-warp smem staging -> fully coalesced float4 stores ----
    float* stage = As + wid * 128;          // fits: 7*128 = 896 <= 1280
    const float inv = 1.0f / 256.0f;
    const int xb = 8 * g + pi;
    float4* outf4 = (float4*)out;
    const int dbase = b * (G_SZ * G_SZ) + dy_idx * G_SZ;

#pragma unroll 1
    for (int d = 0; d < 21; ++d) {
        __syncwarp();
        stage[xb + 0] = acc[0][d] * inv;
        stage[xb + 2] = acc[1][d] * inv;
        stage[xb + 4] = acc[2][d] * inv;
        stage[xb + 6] = acc[3][d] * inv;
        __syncwarp();
        float4 o = ((const float4*)stage)[lane];
        outf4[((dbase + d) * H_SZ + y) * (W_SZ / 4) + lane] = o;
    }
}

extern "C" void kernel_launch(void* const* d_in, const int* in_sizes, int n_in,
                              void* d_out, int out_size)
{
    const float* in1 = (const float*)d_in[0];
    const float* in2 = (const float*)d_in[1];
    float* out = (float*)d_out;

    cudaFuncSetAttribute(corr_kernel,
                         cudaFuncAttributeMaxDynamicSharedMemorySize, SMEM_BYTES);

    dim3 grid(3, H_SZ, B_SZ);   // (dy-triple, y, batch) = 2304 blocks
    corr_kernel<<<grid, NTHREADS, SMEM_BYTES>>>(in1, in2, out);
}